// round 8
// baseline (speedup 1.0000x reference)
#include <cuda_runtime.h>

// Shapes fixed by setup_inputs
#define B_ 64
#define T_ 4096
#define F_ 64
#define H_ 256
#define EPSV 1e-8f

// Scan chunking: lambda=0.5 -> 32-step warm-up error ~0.5^32.
#define CHUNK 64
#define NCHUNK (T_ / CHUNK)        // 64
#define WARM 32

#define NSC (B_ * NCHUNK)          // 4096 scan blocks
#define NFG 1024                   // fg blocks (256 rows each)
#define NM 16                      // mse blocks
#define NB1 (NSC + NFG + NM)       // 5136

#define ND2 128                    // dot blocks in kernel 2

__device__ float g_irrsum[B_ * T_];   // sum_f (1-|ac|) per (b,t)
__device__ float g_fgsum[B_ * T_];    // sum_h fg per (b,t)
__device__ float g_mse[NM];
__device__ float g_dot[ND2];
__device__ unsigned int g_cnt = 0;

// ---------------------------------------------------------------------------
// Kernel 1: independent roles, interleaved 4 scan : 1 fg in bid order so each
// SM hosts both latency-bound scan warps and BW-bound fg warps concurrently.
// ---------------------------------------------------------------------------
__global__ void __launch_bounds__(64) k_main(const float* __restrict__ seq,
                                             const float4* __restrict__ fg,
                                             const float4* __restrict__ inp,
                                             const float4* __restrict__ tgt) {
    __shared__ float ws[2][CHUNK];
    __shared__ float sh[2];

    int tid = threadIdx.x;
    int warp = tid >> 5, lane = tid & 31;
    int bid = blockIdx.x;

    if (bid < NSC + NFG) {
        int gq = bid / 5, r = bid - gq * 5;
        if (r < 4) {
            // ================= scan role =================
            int si = gq * 4 + r;               // 0..4095
            int b = si >> 6;                   // NCHUNK=64
            int chunk = si & 63;
            int t0 = chunk * CHUNK;

            const float* base = seq + (size_t)b * T_ * F_ + tid;
            int first = (chunk == 0);
            int ts = first ? 1 : (t0 - WARM);

            float m = 0.f, v = EPSV, c = 0.f;
            float xl = __ldg(base + (size_t)(ts - 1) * F_);

            // warm-up (no output)
#pragma unroll 8
            for (int t = ts; t < t0; ++t) {
                float xt = __ldg(base + (size_t)t * F_);
                m = 0.5f * (m + xt);
                float d = xt - m;
                v = 0.5f * (v + d * d);
                c = 0.5f * (c + d * (xl - m));
                xl = xt;
            }

            if (first && tid < 2) ws[tid][0] = 0.f;   // t=0 pad: |ac|=0
            int tb = first ? 1 : t0;
#pragma unroll 8
            for (int t = tb; t < t0 + CHUNK; ++t) {
                float xt = __ldg(base + (size_t)t * F_);
                m = 0.5f * (m + xt);
                float d = xt - m;
                v = 0.5f * (v + d * d);
                c = 0.5f * (c + d * (xl - m));
                xl = xt;
                float a = fabsf(c * rsqrtf(v * v + EPSV));
#pragma unroll
                for (int o = 16; o > 0; o >>= 1) a += __shfl_xor_sync(0xffffffffu, a, o);
                if (lane == 0) ws[warp][t - t0] = a;
            }
            __syncthreads();
            // irrsum_t = F - sum_f |ac|
            g_irrsum[b * T_ + t0 + tid] = (float)F_ - ws[0][tid] - ws[1][tid];
        } else {
            // ================= fg role =================
            int fgi = gq;                       // 0..1023, 256 rows each
            const float4* fgb = fg + (size_t)fgi * 256 * (H_ / 4);
            float* outp = g_fgsum + fgi * 256;
            int r0 = warp * 128;                // 128 rows per warp
            for (int rr = r0; rr < r0 + 128; rr += 2) {
                const float4* ra = fgb + (size_t)rr * (H_ / 4);
                const float4* rb = ra + (H_ / 4);
                float4 a0 = ra[lane], a1 = ra[lane + 32];
                float4 b0 = rb[lane], b1 = rb[lane + 32];
                float s0 = (a0.x + a0.y) + (a0.z + a0.w) + (a1.x + a1.y) + (a1.z + a1.w);
                float s1 = (b0.x + b0.y) + (b0.z + b0.w) + (b1.x + b1.y) + (b1.z + b1.w);
#pragma unroll
                for (int o = 16; o > 0; o >>= 1) {
                    s0 += __shfl_xor_sync(0xffffffffu, s0, o);
                    s1 += __shfl_xor_sync(0xffffffffu, s1, o);
                }
                if (lane == 0) { outp[rr] = s0; outp[rr + 1] = s1; }
            }
        }
    } else {
        // ================= MSE role =================
        int mi = bid - (NSC + NFG);
        const int n4 = (B_ * T_) / 4;
        float acc = 0.f;
        for (int i = mi * 64 + tid; i < n4; i += NM * 64) {
            float4 a = inp[i], b = tgt[i];
            float dx = a.x - b.x, dy = a.y - b.y, dz = a.z - b.z, dw = a.w - b.w;
            acc += dx * dx + dy * dy + dz * dz + dw * dw;
        }
#pragma unroll
        for (int o = 16; o > 0; o >>= 1) acc += __shfl_xor_sync(0xffffffffu, acc, o);
        if (lane == 0) sh[warp] = acc;
        __syncthreads();
        if (tid == 0) g_mse[mi] = (sh[0] + sh[1]) * (1.0f / ((float)B_ * T_));
    }
}

// ---------------------------------------------------------------------------
// Kernel 2: dot(g_irrsum, g_fgsum) + combine with MSE partials -> scalar.
// ---------------------------------------------------------------------------
__global__ void __launch_bounds__(256) k_dot(float* __restrict__ out) {
    __shared__ float sh[8];
    __shared__ int is_last;
    int tid = threadIdx.x;
    int warp = tid >> 5, lane = tid & 31;

    const float4* ir4 = (const float4*)g_irrsum;
    const float4* fs4 = (const float4*)g_fgsum;
    const int n4 = (B_ * T_) / 4;

    float acc = 0.f;
    for (int i = blockIdx.x * 256 + tid; i < n4; i += ND2 * 256) {
        float4 a = ir4[i], b = fs4[i];
        acc += a.x * b.x + a.y * b.y + a.z * b.z + a.w * b.w;
    }
#pragma unroll
    for (int o = 16; o > 0; o >>= 1) acc += __shfl_xor_sync(0xffffffffu, acc, o);
    if (lane == 0) sh[warp] = acc;
    __syncthreads();
    if (tid == 0) {
        float s = 0.f;
        for (int w = 0; w < 8; ++w) s += sh[w];
        // ALPHA / (B*T*H*F) = 0.5 / 2^32
        g_dot[blockIdx.x] = s * (0.5f / 4294967296.0f);
        __threadfence();
        unsigned int t = atomicAdd(&g_cnt, 1u);
        is_last = (t == ND2 - 1);
    }
    __syncthreads();
    if (is_last) {
        double s = 0.0;
        for (int i = tid; i < ND2; i += 256) s += (double)g_dot[i];
        if (tid < NM) s += (double)g_mse[tid];
#pragma unroll
        for (int o = 16; o > 0; o >>= 1) s += __shfl_xor_sync(0xffffffffu, s, o);
        __shared__ double sd[8];
        if (lane == 0) sd[warp] = s;
        __syncthreads();
        if (tid == 0) {
            double tot = 0.0;
            for (int w = 0; w < 8; ++w) tot += sd[w];
            out[0] = (float)tot;
            g_cnt = 0;                        // reset for graph replay
        }
    }
}

// ---------------------------------------------------------------------------
extern "C" void kernel_launch(void* const* d_in, const int* in_sizes, int n_in,
                              void* d_out, int out_size) {
    const float* input  = (const float*)d_in[0];
    const float* target = (const float*)d_in[1];
    const float* seq    = (const float*)d_in[2];
    const float* fg     = (const float*)d_in[3];

    k_main<<<NB1, 64>>>(seq, (const float4*)fg,
                        (const float4*)input, (const float4*)target);
    k_dot<<<ND2, 256>>>((float*)d_out);
}

// round 9
// speedup vs baseline: 1.0271x; 1.0271x over previous
#include <cuda_runtime.h>

// Shapes fixed by setup_inputs
#define B_ 64
#define T_ 4096
#define F_ 64
#define H_ 256
#define EPSV 1e-8f

// Chunked scan: lambda=0.5 -> 32-step warm-up error ~0.5^32.
#define CHUNK 64
#define NCHUNK (T_ / CHUNK)        // 64
#define WARM 32

#define NS (B_ * NCHUNK)           // 4096 scan blocks
#define NM 16                      // mse blocks
#define NB (NS + NM)

__device__ float g_part[NB];
__device__ unsigned int g_cnt = 0;

// ---------------------------------------------------------------------------
// Fused kernel (R6 structure; fg phase rebuilt for MLP).
//  [0, NS):  (b, chunk) blocks.
//    Phase 1: fgsum of own 64x256 fg slice. 8 lanes/row, 4 rows/warp-pass,
//             8 independent float4 loads per lane (MLP=8), 3-shfl reduce.
//    Phase 2: EW autocorr scan over seq chunk (thread = f-lane) dotted with
//             smem fgsum.
//  [NS, NB): MSE partial blocks.
//  Last arriving block sums all partials in double, writes scalar.
// ---------------------------------------------------------------------------
__global__ void __launch_bounds__(64) k_main(const float* __restrict__ seq,
                                             const float4* __restrict__ fg,
                                             const float4* __restrict__ inp,
                                             const float4* __restrict__ tgt,
                                             float* __restrict__ out) {
    __shared__ float fgsum_s[CHUNK];
    __shared__ float sh[2];
    __shared__ int is_last;

    int tid = threadIdx.x;
    int warp = tid >> 5, lane = tid & 31;

    if (blockIdx.x < NS) {
        int b = blockIdx.x / NCHUNK;
        int chunk = blockIdx.x % NCHUNK;
        int t0 = chunk * CHUNK;

        // ---- Phase 1: fgsum, high-MLP layout ----
        // warp covers rows [warp*32, warp*32+32): 8 passes x 4 rows.
        // lane -> (sub-row = lane>>3, col0 = lane&7); lane loads float4 cols
        // col0, col0+8, ..., col0+56  (8 independent LDG.128).
        {
            const float4* fgb = fg + (size_t)(b * T_ + t0) * (H_ / 4);
            int sub = lane >> 3;
            int col0 = lane & 7;
#pragma unroll
            for (int pass = 0; pass < 8; ++pass) {
                int r = warp * 32 + pass * 4 + sub;
                const float4* rp = fgb + (size_t)r * (H_ / 4) + col0;
                float4 a0 = rp[0],  a1 = rp[8],  a2 = rp[16], a3 = rp[24];
                float4 a4 = rp[32], a5 = rp[40], a6 = rp[48], a7 = rp[56];
                float s =
                    (((a0.x + a0.y) + (a0.z + a0.w)) + ((a1.x + a1.y) + (a1.z + a1.w))) +
                    (((a2.x + a2.y) + (a2.z + a2.w)) + ((a3.x + a3.y) + (a3.z + a3.w))) +
                    (((a4.x + a4.y) + (a4.z + a4.w)) + ((a5.x + a5.y) + (a5.z + a5.w))) +
                    (((a6.x + a6.y) + (a6.z + a6.w)) + ((a7.x + a7.y) + (a7.z + a7.w)));
                s += __shfl_xor_sync(0xffffffffu, s, 1);
                s += __shfl_xor_sync(0xffffffffu, s, 2);
                s += __shfl_xor_sync(0xffffffffu, s, 4);
                if (col0 == 0) fgsum_s[r] = s;
            }
        }
        __syncthreads();

        // ---- Phase 2: EW autocorrelation scan ----
        const float* base = seq + (size_t)b * T_ * F_ + tid;

        int first = (chunk == 0);
        int ts = first ? 1 : (t0 - WARM);
        float m = 0.f, v = EPSV, c = 0.f;
        float xl = __ldg(base + (size_t)(ts - 1) * F_);
        float acc = first ? fgsum_s[0] : 0.f;      // t=0 pad: irr==1

        // warm-up, no accumulation (chunk > 0 only)
#pragma unroll 8
        for (int t = ts; t < t0; ++t) {
            float xt = __ldg(base + (size_t)t * F_);
            m = 0.5f * (m + xt);
            float d = xt - m;
            v = 0.5f * (v + d * d);
            c = 0.5f * (c + d * (xl - m));
            xl = xt;
        }

        int tb = first ? 1 : t0;
#pragma unroll 8
        for (int t = tb; t < t0 + CHUNK; ++t) {
            float xt = __ldg(base + (size_t)t * F_);
            m = 0.5f * (m + xt);
            float d = xt - m;
            v = 0.5f * (v + d * d);
            c = 0.5f * (c + d * (xl - m));
            xl = xt;
            float ac = c * rsqrtf(v * v + EPSV);
            acc += (1.0f - fabsf(ac)) * fgsum_s[t - t0];
        }

#pragma unroll
        for (int o = 16; o > 0; o >>= 1) acc += __shfl_xor_sync(0xffffffffu, acc, o);
        if (lane == 0) sh[warp] = acc;
        __syncthreads();
        if (tid == 0) {
            // ALPHA / (B*T*H*F) = 0.5 / 2^32
            g_part[blockIdx.x] = (sh[0] + sh[1]) * (0.5f / 4294967296.0f);
        }
    } else {
        // ---- MSE role ----
        int bid = blockIdx.x - NS;
        const int n4 = (B_ * T_) / 4;
        float acc = 0.f;
        for (int i = bid * 64 + tid; i < n4; i += NM * 64) {
            float4 a = inp[i], b = tgt[i];
            float dx = a.x - b.x, dy = a.y - b.y, dz = a.z - b.z, dw = a.w - b.w;
            acc += dx * dx + dy * dy + dz * dz + dw * dw;
        }
#pragma unroll
        for (int o = 16; o > 0; o >>= 1) acc += __shfl_xor_sync(0xffffffffu, acc, o);
        if (lane == 0) sh[warp] = acc;
        __syncthreads();
        if (tid == 0)
            g_part[blockIdx.x] = (sh[0] + sh[1]) * (1.0f / ((float)B_ * T_));
    }

    // ---- last-block finalize (threadfence reduction, graph-replay safe) ----
    if (tid == 0) {
        __threadfence();
        unsigned int t = atomicAdd(&g_cnt, 1u);
        is_last = (t == NB - 1);
    }
    __syncthreads();
    if (is_last) {
        double s = 0.0;
        for (int i = tid; i < NB; i += 64) s += (double)g_part[i];
#pragma unroll
        for (int o = 16; o > 0; o >>= 1) s += __shfl_xor_sync(0xffffffffu, s, o);
        __shared__ double sd[2];
        if (lane == 0) sd[warp] = s;
        __syncthreads();
        if (tid == 0) {
            out[0] = (float)(sd[0] + sd[1]);
            g_cnt = 0;                       // reset for next graph replay
        }
    }
}

// ---------------------------------------------------------------------------
extern "C" void kernel_launch(void* const* d_in, const int* in_sizes, int n_in,
                              void* d_out, int out_size) {
    const float* input  = (const float*)d_in[0];
    const float* target = (const float*)d_in[1];
    const float* seq    = (const float*)d_in[2];
    const float* fg     = (const float*)d_in[3];

    k_main<<<NB, 64>>>(seq, (const float4*)fg,
                       (const float4*)input, (const float4*)target,
                       (float*)d_out);
}